// round 9
// baseline (speedup 1.0000x reference)
#include <cuda_runtime.h>
#include <math.h>

#define N_REGS 32
#define KEY_DIM 128
#define BIT_WIDTH 64
#define TAB_VEC4 (N_REGS * BIT_WIDTH / 4)   // 512
#define THREADS 256
#define GRID 888                             // 148 SMs * 6 CTAs = one resident wave
#define STAGE_VEC4 512                       // 8 KB per TMA bulk store
#define FLAG_STRIDE 32                       // one 128B line per flag copy

// Precomputed output table: one 64-float row per idx value. 8 KB.
__device__ float g_table[N_REGS * BIT_WIDTH];
// Handshake state, each element on its own 128B line.
__device__ __align__(128) unsigned g_go_arr[N_REGS * FLAG_STRIDE];
__device__ __align__(128) unsigned g_ready[FLAG_STRIDE];
__device__ __align__(128) unsigned g_done[FLAG_STRIDE];

__device__ __forceinline__ float gelu_exact(float x) {
    return 0.5f * x * (1.0f + erff(x * 0.70710678118654752440f));
}

__device__ __forceinline__ void l2_prefetch(const void* p) {
    asm volatile("prefetch.global.L2 [%0];" :: "l"(p));
}

__device__ __forceinline__ unsigned smem_u32(const void* p) {
    return (unsigned)__cvta_generic_to_shared(p);
}

__global__ void __launch_bounds__(THREADS, 6) fused_kernel(
    const int*   __restrict__ idx,
    const float* __restrict__ W1,          // [5, 128]
    const float* __restrict__ b1,          // [128]
    const float* __restrict__ W2,          // [128, 128]
    const float* __restrict__ b2,          // [128]
    const float* __restrict__ keys,        // [32, 128]
    const float* __restrict__ temperature, // scalar
    const float* __restrict__ rv,          // [32, 64]
    float4*      __restrict__ out,
    int total_vec4)                        // = B * 16
{
    __shared__ float4 stab[TAB_VEC4];                       // 8 KB staged table
    __shared__ __align__(128) float4 obuf[2][STAGE_VEC4];   // 2 x 8 KB out tiles

    const int tid = threadIdx.x;

    // Block-contiguous output partition: block b owns [start, end) float4s.
    const int per   = (total_vec4 + GRID - 1) / GRID;
    const int start = (int)blockIdx.x * per;
    const int end   = min(start + per, total_vec4);

    // ------------- Producer phase: blocks 0..31 build one table row each ----
    if (blockIdx.x < N_REGS) {
        __shared__ float sh_h[KEY_DIM];
        __shared__ float sh_qp[2 * KEY_DIM];
        __shared__ float sh_a[N_REGS];

        // 0) Fire-and-forget L2 prefetch of every weight line.
        l2_prefetch((const char*)W2 + tid * 256);
        l2_prefetch((const char*)W2 + tid * 256 + 128);
        if (tid < 128) l2_prefetch((const char*)keys + tid * 128);
        if (tid >= 128 && tid < 192) l2_prefetch((const char*)rv + (tid - 128) * 128);

        const int idv = (int)blockIdx.x;

        // 1) h = gelu(bits @ W1 + b1)
        if (tid < KEY_DIM) {
            float acc = b1[tid];
            #pragma unroll
            for (int k = 0; k < 5; k++)
                if ((idv >> k) & 1) acc += W1[k * KEY_DIM + tid];
            sh_h[tid] = gelu_exact(acc);
        }
        __syncthreads();

        // 2) query = h @ W2 + b2, split-j across all 256 threads
        {
            const int o = tid & 127, half = tid >> 7;
            float part = (half == 0) ? b2[o] : 0.0f;
            const int j0 = half * 64;
            #pragma unroll 16
            for (int j = j0; j < j0 + 64; j++)
                part = fmaf(sh_h[j], W2[j * KEY_DIM + o], part);
            sh_qp[half * KEY_DIM + o] = part;
        }
        __syncthreads();
        if (tid < KEY_DIM)
            sh_qp[tid] = sh_qp[tid] + sh_qp[KEY_DIM + tid];
        __syncthreads();

        // 3) sim[r] = q . keys[r], 8 lanes per register row
        {
            const int r = tid >> 3, part = tid & 7;
            float s = 0.0f;
            #pragma unroll 16
            for (int i = part * 16; i < part * 16 + 16; i++)
                s = fmaf(sh_qp[i], keys[r * KEY_DIM + i], s);
            s += __shfl_xor_sync(0xffffffffu, s, 1);
            s += __shfl_xor_sync(0xffffffffu, s, 2);
            s += __shfl_xor_sync(0xffffffffu, s, 4);
            if (part == 0) sh_a[r] = s;
        }
        __syncthreads();

        // 4) softmax over 32 (warp 0)
        if (tid < N_REGS) {
            float temp = fmaxf(fabsf(temperature[0]), 0.1f);
            float s = sh_a[tid] / temp;
            float m = s;
            #pragma unroll
            for (int off = 16; off > 0; off >>= 1)
                m = fmaxf(m, __shfl_xor_sync(0xffffffffu, m, off));
            float e = expf(s - m);
            float sum = e;
            #pragma unroll
            for (int off = 16; off > 0; off >>= 1)
                sum += __shfl_xor_sync(0xffffffffu, sum, off);
            sh_a[tid] = e / sum;
        }
        __syncthreads();

        // 5) table row = attn @ register_values; XZR (idx==31) forced to zero
        if (tid < BIT_WIDTH) {
            float v = 0.0f;
            #pragma unroll
            for (int r = 0; r < N_REGS; r++)
                v = fmaf(sh_a[r], rv[r * BIT_WIDTH + tid], v);
            if (idv == 31) v = 0.0f;
            g_table[idv * BIT_WIDTH + tid] = v;
        }
        __syncthreads();
        __threadfence();
        if (tid == 0) {
            unsigned prev = atomicAdd(&g_ready[0], 1u);
            if (prev == N_REGS - 1) {
                __threadfence();
                for (int f = 0; f < N_REGS; f++)
                    *(volatile unsigned*)&g_go_arr[f * FLAG_STRIDE] = 1u;
            }
        }
    } else {
        // Consumers: warm L2/L1 with our contiguous idx slice (~4.7KB).
        const int row0  = start >> 4;
        const int nrows = (end > start) ? ((end - 1) >> 4) - row0 + 1 : 0;
        for (int w = tid * 32; w < nrows; w += THREADS * 32)
            l2_prefetch(idx + row0 + w);
    }

    // ------------- Handshake: sharded plain-load poll, tight cap -------------
    if (tid == 0) {
        volatile unsigned* flag = &g_go_arr[(blockIdx.x & (N_REGS - 1)) * FLAG_STRIDE];
        unsigned delay = 64u + ((blockIdx.x >> 5) & 7u) * 16u;
        while (*flag == 0u) {
            __nanosleep(delay);
            delay = min(delay + delay, 256u);
        }
    }
    __syncthreads();

    // Stage table into smem (__ldcg: L1-bypass, coherent with builders' L2 data).
    const float4* gt = reinterpret_cast<const float4*>(g_table);
    for (int t = tid; t < TAB_VEC4; t += THREADS)
        stab[t] = __ldcg(&gt[t]);
    __syncthreads();

    // ------------- Consumer phase: smem-tiled gather + TMA bulk stores -------
    // Each stage: fill an 8KB smem tile (LDG idx -> LDS table -> STS), then one
    // elected thread issues cp.async.bulk smem->gmem. Double-buffered;
    // wait_group.read 1 gates buffer reuse. Stores leave via the TMA/bulk path
    // in 8KB contiguous bursts instead of per-warp STG.128.
    const int nstages = (end - start + STAGE_VEC4 - 1) / STAGE_VEC4;

    for (int s = 0; s < nstages; s++) {
        const int buf   = s & 1;
        const int tile0 = start + s * STAGE_VEC4;
        const int chunk = min(STAGE_VEC4, end - tile0);

        // Gate reuse of this buffer: allow at most 1 outstanding group (the
        // other buffer) before refilling.
        if (s >= 2) {
            if (tid == 0)
                asm volatile("cp.async.bulk.wait_group.read 1;" ::: "memory");
            __syncthreads();
        }

        // Fill tile: each thread handles <=2 float4.
        #pragma unroll
        for (int k = tid; k < chunk; k += THREADS) {
            int t  = tile0 + k;
            int rr = __ldg(&idx[t >> 4]);
            obuf[buf][k] = stab[(rr << 4) + (t & 15)];
        }
        __syncthreads();

        if (tid == 0) {
            asm volatile("fence.proxy.async.shared::cta;" ::: "memory");
            unsigned saddr = smem_u32(&obuf[buf][0]);
            const float4* gdst = out + tile0;
            unsigned bytes = (unsigned)chunk * 16u;
            asm volatile(
                "cp.async.bulk.global.shared::cta.bulk_group [%0], [%1], %2;"
                :: "l"(gdst), "r"(saddr), "r"(bytes) : "memory");
            asm volatile("cp.async.bulk.commit_group;" ::: "memory");
        }
    }
    // Drain all outstanding bulk stores before exit.
    if (tid == 0)
        asm volatile("cp.async.bulk.wait_group 0;" ::: "memory");

    // ------------- Reset flags for the next graph replay ---------------------
    __syncthreads();
    if (tid == 0) {
        unsigned old = atomicAdd(&g_done[0], 1u);
        if (old == (unsigned)(gridDim.x - 1)) {
            for (int f = 0; f < N_REGS; f++)
                *(volatile unsigned*)&g_go_arr[f * FLAG_STRIDE] = 0u;
            atomicExch(&g_ready[0], 0u);
            atomicExch(&g_done[0], 0u);
            __threadfence();
        }
    }
}

extern "C" void kernel_launch(void* const* d_in, const int* in_sizes, int n_in,
                              void* d_out, int out_size)
{
    const int*   idx  = (const int*)  d_in[0];
    const float* W1   = (const float*)d_in[1];
    const float* b1   = (const float*)d_in[2];
    const float* W2   = (const float*)d_in[3];
    const float* b2   = (const float*)d_in[4];
    const float* keys = (const float*)d_in[5];
    const float* temp = (const float*)d_in[6];
    const float* rv   = (const float*)d_in[7];

    const int B = in_sizes[0];
    const int total_vec4 = B * (BIT_WIDTH / 4);   // B * 16

    fused_kernel<<<GRID, THREADS>>>(idx, W1, b1, W2, b2, keys, temp, rv,
                                    (float4*)d_out, total_vec4);
}

// round 10
// speedup vs baseline: 1.1333x; 1.1333x over previous
#include <cuda_runtime.h>
#include <math.h>

#define N_REGS 32
#define KEY_DIM 128
#define BIT_WIDTH 64
#define TAB_VEC4 (N_REGS * BIT_WIDTH / 4)   // 512
#define BTHREADS 256
#define GTHREADS 256
#define GGRID 1184                           // 148 SMs * 8 CTAs (R2-proven config)
#define UNROLL 4

// Precomputed output table: one 64-float row per idx value. 8 KB.
__device__ float g_table[N_REGS * BIT_WIDTH];

__device__ __forceinline__ float gelu_exact(float x) {
    return 0.5f * x * (1.0f + erff(x * 0.70710678118654752440f));
}

__device__ __forceinline__ void l2_prefetch(const void* p) {
    asm volatile("prefetch.global.L2 [%0];" :: "l"(p));
}

// ---------------- Build kernel: 32 blocks, one table row each ----------------
__global__ void __launch_bounds__(BTHREADS) build_kernel(
    const float* __restrict__ W1,          // [5, 128]
    const float* __restrict__ b1,          // [128]
    const float* __restrict__ W2,          // [128, 128]
    const float* __restrict__ b2,          // [128]
    const float* __restrict__ keys,        // [32, 128]
    const float* __restrict__ temperature, // scalar
    const float* __restrict__ rv)          // [32, 64]
{
    // Let the dependent (gather) grid start ramping immediately; it will
    // cudaGridDependencySynchronize() before touching our output.
    cudaTriggerProgrammaticLaunchCompletion();

    __shared__ float sh_h[KEY_DIM];
    __shared__ float sh_qp[2 * KEY_DIM];
    __shared__ float sh_a[N_REGS];

    const int tid = threadIdx.x;
    const int idv = (int)blockIdx.x;

    // 0) Fire-and-forget L2 prefetch of every weight line.
    l2_prefetch((const char*)W2 + tid * 256);
    l2_prefetch((const char*)W2 + tid * 256 + 128);
    if (tid < 128) l2_prefetch((const char*)keys + tid * 128);
    if (tid >= 128 && tid < 192) l2_prefetch((const char*)rv + (tid - 128) * 128);

    // 1) h = gelu(bits @ W1 + b1)
    if (tid < KEY_DIM) {
        float acc = b1[tid];
        #pragma unroll
        for (int k = 0; k < 5; k++)
            if ((idv >> k) & 1) acc += W1[k * KEY_DIM + tid];
        sh_h[tid] = gelu_exact(acc);
    }
    __syncthreads();

    // 2) query = h @ W2 + b2, split-j across all 256 threads
    {
        const int o = tid & 127, half = tid >> 7;
        float part = (half == 0) ? b2[o] : 0.0f;
        const int j0 = half * 64;
        #pragma unroll 16
        for (int j = j0; j < j0 + 64; j++)
            part = fmaf(sh_h[j], W2[j * KEY_DIM + o], part);
        sh_qp[half * KEY_DIM + o] = part;
    }
    __syncthreads();
    if (tid < KEY_DIM)
        sh_qp[tid] = sh_qp[tid] + sh_qp[KEY_DIM + tid];
    __syncthreads();

    // 3) sim[r] = q . keys[r], 8 lanes per register row
    {
        const int r = tid >> 3, part = tid & 7;
        float s = 0.0f;
        #pragma unroll 16
        for (int i = part * 16; i < part * 16 + 16; i++)
            s = fmaf(sh_qp[i], keys[r * KEY_DIM + i], s);
        s += __shfl_xor_sync(0xffffffffu, s, 1);
        s += __shfl_xor_sync(0xffffffffu, s, 2);
        s += __shfl_xor_sync(0xffffffffu, s, 4);
        if (part == 0) sh_a[r] = s;
    }
    __syncthreads();

    // 4) softmax over 32 (warp 0)
    if (tid < N_REGS) {
        float temp = fmaxf(fabsf(temperature[0]), 0.1f);
        float s = sh_a[tid] / temp;
        float m = s;
        #pragma unroll
        for (int off = 16; off > 0; off >>= 1)
            m = fmaxf(m, __shfl_xor_sync(0xffffffffu, m, off));
        float e = expf(s - m);
        float sum = e;
        #pragma unroll
        for (int off = 16; off > 0; off >>= 1)
            sum += __shfl_xor_sync(0xffffffffu, sum, off);
        sh_a[tid] = e / sum;
    }
    __syncthreads();

    // 5) table row = attn @ register_values; XZR (idx==31) forced to zero
    if (tid < BIT_WIDTH) {
        float v = 0.0f;
        #pragma unroll
        for (int r = 0; r < N_REGS; r++)
            v = fmaf(sh_a[r], rv[r * BIT_WIDTH + tid], v);
        if (idv == 31) v = 0.0f;
        g_table[idv * BIT_WIDTH + tid] = v;
    }
    // Grid completion (which griddepsync in the gather waits on) makes these
    // writes visible; no explicit fence needed.
}

// ---------------- Gather kernel (PDL secondary): R2-proven config ------------
__global__ void __launch_bounds__(GTHREADS, 8) gather_kernel(
    const int* __restrict__ idx,
    float4* __restrict__ out,
    int total_vec4)   // = B * 16
{
    __shared__ float4 stab[TAB_VEC4];  // 8 KB

    const int tid  = threadIdx.x;
    const int step = GGRID * GTHREADS;
    int base = (int)blockIdx.x * GTHREADS + tid;

    // Preamble (overlaps with the build kernel under PDL): warm L2 with a
    // contiguous slice of the 4MB idx array. ~3.5KB per block.
    {
        const int nrows = total_vec4 >> 4;
        const int wpb   = (nrows + GGRID - 1) / GGRID;
        const int s0    = (int)blockIdx.x * wpb;
        for (int w = s0 + tid * 32; w < s0 + wpb && w < nrows; w += GTHREADS * 32)
            l2_prefetch(idx + w);
    }

    // Wait for the build grid to complete (and its g_table writes to be visible).
    cudaGridDependencySynchronize();

    // Stage table into smem.
    const float4* gt = reinterpret_cast<const float4*>(g_table);
    for (int i = tid; i < TAB_VEC4; i += GTHREADS)
        stab[i] = __ldcg(&gt[i]);
    __syncthreads();

    // Grid-stride gather. Element stride = GGRID*GTHREADS (0 mod 16):
    // c = t & 15 constant per thread -> coalesced stores, conflict-free smem.
    for (; base + (UNROLL - 1) * step < total_vec4; base += UNROLL * step) {
        int r[UNROLL];
        #pragma unroll
        for (int u = 0; u < UNROLL; u++)
            r[u] = __ldg(&idx[(base + u * step) >> 4]);    // MLP=UNROLL
        float4 v[UNROLL];
        #pragma unroll
        for (int u = 0; u < UNROLL; u++)
            v[u] = stab[(r[u] << 4) + ((base + u * step) & 15)];
        #pragma unroll
        for (int u = 0; u < UNROLL; u++)
            out[base + u * step] = v[u];                   // plain STG.128
    }
    for (; base < total_vec4; base += step) {
        int rr = __ldg(&idx[base >> 4]);
        out[base] = stab[(rr << 4) + (base & 15)];
    }
}

extern "C" void kernel_launch(void* const* d_in, const int* in_sizes, int n_in,
                              void* d_out, int out_size)
{
    const int*   idx  = (const int*)  d_in[0];
    const float* W1   = (const float*)d_in[1];
    const float* b1   = (const float*)d_in[2];
    const float* W2   = (const float*)d_in[3];
    const float* b2   = (const float*)d_in[4];
    const float* keys = (const float*)d_in[5];
    const float* temp = (const float*)d_in[6];
    const float* rv   = (const float*)d_in[7];

    const int B = in_sizes[0];
    const int total_vec4 = B * (BIT_WIDTH / 4);   // B * 16

    build_kernel<<<N_REGS, BTHREADS>>>(W1, b1, W2, b2, keys, temp, rv);

    // Launch the gather as a PDL secondary: its CTAs may begin (ramp + idx
    // prefetch) while build_kernel runs; cudaGridDependencySynchronize()
    // inside provides the ordering on g_table.
    cudaLaunchAttribute attrs[1];
    attrs[0].id = cudaLaunchAttributeProgrammaticStreamSerialization;
    attrs[0].val.programmaticStreamSerializationAllowed = 1;

    cudaLaunchConfig_t cfg = {};
    cfg.gridDim  = dim3(GGRID, 1, 1);
    cfg.blockDim = dim3(GTHREADS, 1, 1);
    cfg.dynamicSmemBytes = 0;
    cfg.stream = 0;
    cfg.attrs = attrs;
    cfg.numAttrs = 1;

    cudaLaunchKernelEx(&cfg, gather_kernel, idx, (float4*)d_out, total_vec4);
}